// round 1
// baseline (speedup 1.0000x reference)
#include <cuda_runtime.h>
#include <cuda_bf16.h>

#define NBINS 36
#define PS 32
#define WPC 8                 // warps (patches) per CTA
#define THREADS (WPC * 32)

#define TWO_PI_F 6.28318530717958647692f   // rounds to 0x40C90FDB
#define PI_F     3.14159265358979323846f   // rounds to 0x40490FDB

__global__ void __launch_bounds__(THREADS)
orientation_kernel(const float* __restrict__ x,
                   const float* __restrict__ gxw,
                   const float* __restrict__ gyw,
                   const float* __restrict__ smw,
                   const float* __restrict__ gk,
                   float* __restrict__ out,
                   int B)
{
    __shared__ float gks[PS * PS];
    __shared__ float hist[WPC][NBINS];

    const int tid  = threadIdx.x;
    const int lane = tid & 31;
    const int w    = tid >> 5;
    const int patch = blockIdx.x * WPC + w;

    // Stage gk (4 KB) into shared, zero this warp's histogram.
    for (int i = tid; i < PS * PS; i += THREADS) gks[i] = gk[i];
    hist[w][lane] = 0.0f;
    if (lane < NBINS - 32) hist[w][lane + 32] = 0.0f;
    __syncthreads();

    if (patch >= B) return;   // whole warp exits together; no __syncthreads below

    // Gradient weights (tiny, L1-resident)
    const float g0 = __ldg(gxw + 0), g1 = __ldg(gxw + 1), g2 = __ldg(gxw + 2);
    const float h0 = __ldg(gyw + 0), h1 = __ldg(gyw + 1), h2 = __ldg(gyw + 2);

    const float* p = x + (size_t)patch * (PS * PS) + lane;
    const int sl = (lane > 0)  ? lane - 1 : 0;    // replicate-pad left
    const int sr = (lane < 31) ? lane + 1 : 31;   // replicate-pad right

    float cur = __ldg(p);     // row 0
    float prv = cur;          // replicate-pad top
    float* hrow = hist[w];

    #pragma unroll 4
    for (int r = 0; r < PS; ++r) {
        const float nxt = (r + 1 < PS) ? __ldg(p + (r + 1) * PS) : cur; // replicate-pad bottom
        const float lft = __shfl_sync(0xffffffffu, cur, sl);
        const float rgt = __shfl_sync(0xffffffffu, cur, sr);

        // gx = g0*l + g1*c + g2*r   (explicit mul/add: match XLA, no FMA contraction)
        const float gx = __fadd_rn(__fadd_rn(__fmul_rn(g0, lft), __fmul_rn(g1, cur)),
                                   __fmul_rn(g2, rgt));
        const float gy = __fadd_rn(__fadd_rn(__fmul_rn(h0, prv), __fmul_rn(h1, cur)),
                                   __fmul_rn(h2, nxt));

        const float m2  = __fadd_rn(__fadd_rn(__fmul_rn(gx, gx), __fmul_rn(gy, gy)), 1e-10f);
        const float mag = __fmul_rn(__fsqrt_rn(m2), gks[r * PS + lane]);

        if (mag > 0.001f) {
            const float ori = atan2f(gy, gx);                       // libdevice, matches XLA-GPU
            const float rr  = (ori < 0.0f) ? __fadd_rn(ori, TWO_PI_F) : ori;  // jnp.mod(ori,2pi)
            const float ob  = __fdiv_rn(__fmul_rn(36.0f, rr), TWO_PI_F);      // ref op order
            const float bf  = floorf(ob);
            const float wo1 = __fsub_rn(ob, bf);
            const float wt  = __fmul_rn(__fsub_rn(1.0f, wo1), mag);
            int bin = (int)bf;
            if (bin >= NBINS) bin -= NBINS;                         // jnp.mod(bo0f, 36)
            atomicAdd(hrow + bin, wt);
        }
        prv = cur; cur = nxt;
    }
    __syncwarp();

    // ---- angular smoothing (zero-padded conv3) + first-index argmax ----
    const float s0 = __ldg(smw + 0), s1 = __ldg(smw + 1), s2 = __ldg(smw + 2);
    // Note: skipping hist/(H*W): exact power-of-2 scale, argmax-invariant.

    // Candidate A: bin = lane (0..31)
    {
    }
    const float a1 = (lane > 0) ? hrow[lane - 1] : 0.0f;
    const float m1 = hrow[lane];
    const float c1 = hrow[lane + 1];                 // lane 31 -> bin 32, valid
    float v1 = __fadd_rn(__fadd_rn(__fmul_rn(s0, a1), __fmul_rn(s1, m1)),
                         __fmul_rn(s2, c1));

    // Candidate B: bins 32..35 on lanes 0..3
    float v2 = -1.0f;                                // hist >= 0 so never wins
    if (lane < 4) {
        const int b = lane + 32;
        const float a2 = hrow[b - 1];
        const float m2v = hrow[b];
        const float c2 = (b < NBINS - 1) ? hrow[b + 1] : 0.0f;
        v2 = __fadd_rn(__fadd_rn(__fmul_rn(s0, a2), __fmul_rn(s1, m2v)),
                       __fmul_rn(s2, c2));
    }

    // local merge, prefer lower bin index on tie (first occurrence)
    float bv; int bi;
    if (v2 > v1) { bv = v2; bi = lane + 32; }
    else         { bv = v1; bi = lane; }

    #pragma unroll
    for (int off = 16; off > 0; off >>= 1) {
        const float ov = __shfl_xor_sync(0xffffffffu, bv, off);
        const int   oi = __shfl_xor_sync(0xffffffffu, bi, off);
        if (ov > bv || (ov == bv && oi < bi)) { bv = ov; bi = oi; }
    }

    if (lane == 0) {
        // angle = -(2*pi*idx/36 - pi), replicating ref op order
        const float t = __fdiv_rn(__fmul_rn(TWO_PI_F, (float)bi), 36.0f);
        out[patch] = -__fsub_rn(t, PI_F);
    }
}

extern "C" void kernel_launch(void* const* d_in, const int* in_sizes, int n_in,
                              void* d_out, int out_size) {
    const float* x   = (const float*)d_in[0];
    const float* gxw = (const float*)d_in[1];
    const float* gyw = (const float*)d_in[2];
    const float* smw = (const float*)d_in[3];
    const float* gk  = (const float*)d_in[4];
    float* out = (float*)d_out;
    const int B = out_size;
    const int grid = (B + WPC - 1) / WPC;
    orientation_kernel<<<grid, THREADS>>>(x, gxw, gyw, smw, gk, out, B);
}